// round 1
// baseline (speedup 1.0000x reference)
#include <cuda_runtime.h>
#include <math.h>

// Problem constants
#define M_ROWS 16384
#define N_COLS 1000
#define K_DIM  4096
#define NUM_TTA_ 64
#define KEPT 6          // int(0.1 * 64)
#define NBATCH 256      // 16384 / 64

// Scratch (device globals: allocation-free per harness rules)
__device__ float g_logits[(size_t)M_ROWS * N_COLS];
__device__ float g_ent[M_ROWS];
__device__ int   g_vote[M_ROWS];

// ----------------------------------------------------------------------------
// Packed f32x2 helpers (FFMA2 — 2x fp32 FMA throughput vs 3-reg FFMA on sm_103a)
// ----------------------------------------------------------------------------
__device__ __forceinline__ unsigned long long pack2(float lo, float hi) {
    unsigned long long r;
    asm("mov.b64 %0, {%1, %2};" : "=l"(r) : "f"(lo), "f"(hi));
    return r;
}
__device__ __forceinline__ void fma2(unsigned long long& d,
                                     unsigned long long a,
                                     unsigned long long b) {
    asm("fma.rn.f32x2 %0, %1, %2, %0;" : "+l"(d) : "l"(a), "l"(b));
}
__device__ __forceinline__ void unpack2(unsigned long long v, float& lo, float& hi) {
    asm("mov.b64 {%0, %1}, %2;" : "=f"(lo), "=f"(hi) : "l"(v));
}

// ----------------------------------------------------------------------------
// Kernel A: fp32 SGEMM  logits = x @ W + b
// 128x128 block tile, BK=8, 256 threads, 8x8 microtile, f32x2 packed FMA,
// double-buffered smem, float4 global loads.
// ----------------------------------------------------------------------------
#define BM 128
#define BN 128
#define BK 8

__global__ __launch_bounds__(256, 1)
void sgemm_kernel(const float* __restrict__ x,
                  const float* __restrict__ W,
                  const float* __restrict__ bias) {
    __shared__ float As[2][BK][BM];   // transposed A tile
    __shared__ float Bs[2][BK][BN];

    const int tid = threadIdx.x;
    const int n0 = blockIdx.x * BN;
    const int m0 = blockIdx.y * BM;

    // A-tile load mapping: 128 rows x 8 cols -> each thread 1 float4
    const int a_row = tid >> 1;
    const int a_col = (tid & 1) << 2;
    // B-tile load mapping: 8 rows x 128 cols -> each thread 1 float4
    const int b_row = tid >> 5;
    const int b_col = (tid & 31) << 2;
    const bool b_valid = (n0 + b_col + 3) < N_COLS;   // 1000 % 4 == 0: vector fully in or out

    const float* xg = x + (size_t)(m0 + a_row) * K_DIM + a_col;

    // microtile mapping
    const int tx = tid & 15;   // 16 cols of threads
    const int ty = tid >> 4;   // 16 rows of threads

    unsigned long long c2[8][4];
#pragma unroll
    for (int i = 0; i < 8; i++)
#pragma unroll
        for (int j = 0; j < 4; j++) c2[i][j] = 0ull;

    const int KT = K_DIM / BK;   // 512

    // preload tile 0
    {
        float4 av = *(const float4*)(xg);
        float4 bv = make_float4(0.f, 0.f, 0.f, 0.f);
        if (b_valid) bv = *(const float4*)(W + (size_t)b_row * N_COLS + n0 + b_col);
        As[0][a_col + 0][a_row] = av.x;
        As[0][a_col + 1][a_row] = av.y;
        As[0][a_col + 2][a_row] = av.z;
        As[0][a_col + 3][a_row] = av.w;
        *(float4*)&Bs[0][b_row][b_col] = bv;
    }
    __syncthreads();

    int buf = 0;
    for (int kt = 0; kt < KT; kt++) {
        float4 av, bv;
        const bool more = (kt + 1) < KT;
        if (more) {
            av = *(const float4*)(xg + (size_t)(kt + 1) * BK);
            bv = make_float4(0.f, 0.f, 0.f, 0.f);
            if (b_valid)
                bv = *(const float4*)(W + (size_t)((kt + 1) * BK + b_row) * N_COLS + n0 + b_col);
        }

        const float(*Ac)[BM] = As[buf];
        const float(*Bc)[BN] = Bs[buf];

#pragma unroll
        for (int k = 0; k < BK; k++) {
            float4 a0 = *(const float4*)&Ac[k][ty * 8];
            float4 a1 = *(const float4*)&Ac[k][ty * 8 + 4];
            float4 bb0 = *(const float4*)&Bc[k][tx * 8];
            float4 bb1 = *(const float4*)&Bc[k][tx * 8 + 4];
            unsigned long long b2[4];
            b2[0] = pack2(bb0.x, bb0.y);
            b2[1] = pack2(bb0.z, bb0.w);
            b2[2] = pack2(bb1.x, bb1.y);
            b2[3] = pack2(bb1.z, bb1.w);
            float avr[8] = {a0.x, a0.y, a0.z, a0.w, a1.x, a1.y, a1.z, a1.w};
#pragma unroll
            for (int i = 0; i < 8; i++) {
                unsigned long long a2 = pack2(avr[i], avr[i]);
#pragma unroll
                for (int j = 0; j < 4; j++) fma2(c2[i][j], a2, b2[j]);
            }
        }

        if (more) {
            int nb = buf ^ 1;
            As[nb][a_col + 0][a_row] = av.x;
            As[nb][a_col + 1][a_row] = av.y;
            As[nb][a_col + 2][a_row] = av.z;
            As[nb][a_col + 3][a_row] = av.w;
            *(float4*)&Bs[nb][b_row][b_col] = bv;
        }
        __syncthreads();
        buf ^= 1;
    }

    // epilogue: add bias, write logits (float2, column-pair granularity)
#pragma unroll
    for (int i = 0; i < 8; i++) {
        const int row = m0 + ty * 8 + i;
#pragma unroll
        for (int j = 0; j < 4; j++) {
            const int col = n0 + tx * 8 + j * 2;
            if (col < N_COLS) {   // cols come in even pairs; 1000 is even
                float lo, hi;
                unpack2(c2[i][j], lo, hi);
                float2 o;
                o.x = lo + bias[col];
                o.y = hi + bias[col + 1];
                *(float2*)&g_logits[(size_t)row * N_COLS + col] = o;
            }
        }
    }
}

// ----------------------------------------------------------------------------
// Kernel B: per-row argmax (first-index tie-break) + softmax entropy
//   H = log(S) - T/S, S = sum e^{z-m}, T = sum (z-m) e^{z-m}
// ----------------------------------------------------------------------------
__global__ __launch_bounds__(128)
void rowstats_kernel() {
    const int row = blockIdx.x;
    const float* z = g_logits + (size_t)row * N_COLS;
    const int tid = threadIdx.x;

    __shared__ float smx[128];
    __shared__ int smi[128];
    __shared__ float sS[128];
    __shared__ float sT[128];

    // pass 1: max + argmax (ascending scan keeps first occurrence per thread)
    float mx = -3.4e38f;
    int mi = 0x7fffffff;
    for (int c = tid; c < N_COLS; c += 128) {
        float v = z[c];
        if (v > mx) { mx = v; mi = c; }
    }
    smx[tid] = mx; smi[tid] = mi;
    __syncthreads();
    for (int s = 64; s > 0; s >>= 1) {
        if (tid < s) {
            float vo = smx[tid + s]; int io = smi[tid + s];
            if (vo > smx[tid] || (vo == smx[tid] && io < smi[tid])) {
                smx[tid] = vo; smi[tid] = io;
            }
        }
        __syncthreads();
    }
    const float m = smx[0];
    const int vote = smi[0];
    __syncthreads();

    // pass 2: S and T
    float S = 0.f, T = 0.f;
    for (int c = tid; c < N_COLS; c += 128) {
        float u = z[c] - m;
        float e = expf(u);
        S += e;
        T += u * e;
    }
    sS[tid] = S; sT[tid] = T;
    __syncthreads();
    for (int s = 64; s > 0; s >>= 1) {
        if (tid < s) { sS[tid] += sS[tid + s]; sT[tid] += sT[tid + s]; }
        __syncthreads();
    }
    if (tid == 0) {
        g_ent[row] = logf(sS[0]) - sT[0] / sS[0];
        g_vote[row] = vote;
    }
}

// ----------------------------------------------------------------------------
// Kernel C: per-batch voting.
//   stable argsort of 64 entropies (rank by comparison), top-6 votes -> counts,
//   58 sequential tie-augmentation steps, out = log(counts/64 + 1e-8)
// ----------------------------------------------------------------------------
__global__ __launch_bounds__(256)
void vote_kernel(float* __restrict__ out) {
    __shared__ float ent_s[NUM_TTA_];
    __shared__ int sv[NUM_TTA_];       // votes in confidence order
    __shared__ int counts[N_COLS];
    __shared__ int rmx[256];
    __shared__ int rcnt[256];

    const int b = blockIdx.x;
    const int tid = threadIdx.x;

    if (tid < NUM_TTA_) ent_s[tid] = g_ent[b * NUM_TTA_ + tid];
    for (int c = tid; c < N_COLS; c += 256) counts[c] = 0;
    __syncthreads();

    if (tid < NUM_TTA_) {
        float e = ent_s[tid];
        int r = 0;
#pragma unroll
        for (int j = 0; j < NUM_TTA_; j++) {
            float ej = ent_s[j];
            r += (ej < e) || (ej == e && j < tid);   // stable ascending rank
        }
        sv[r] = g_vote[b * NUM_TTA_ + tid];
    }
    __syncthreads();

    if (tid == 0) {
        for (int i = 0; i < KEPT; i++) counts[sv[i]]++;
    }
    __syncthreads();

    for (int i = 0; i < NUM_TTA_ - KEPT; i++) {
        int mx = -1, cnt = 0;
        for (int c = tid; c < N_COLS; c += 256) {
            int v = counts[c];
            if (v > mx) { mx = v; cnt = 1; }
            else if (v == mx) cnt++;
        }
        rmx[tid] = mx; rcnt[tid] = cnt;
        __syncthreads();
        for (int s = 128; s > 0; s >>= 1) {
            if (tid < s) {
                if (rmx[tid + s] > rmx[tid]) { rmx[tid] = rmx[tid + s]; rcnt[tid] = rcnt[tid + s]; }
                else if (rmx[tid + s] == rmx[tid]) rcnt[tid] += rcnt[tid + s];
            }
            __syncthreads();
        }
        if (tid == 0 && rcnt[0] > 1) counts[sv[KEPT + i]] += 1;
        __syncthreads();
    }

    for (int c = tid; c < N_COLS; c += 256) {
        out[(size_t)b * N_COLS + c] = logf((float)counts[c] * (1.0f / 64.0f) + 1e-8f);
    }
}

// ----------------------------------------------------------------------------
extern "C" void kernel_launch(void* const* d_in, const int* in_sizes, int n_in,
                              void* d_out, int out_size) {
    const float* x = (const float*)d_in[0];
    const float* W = (const float*)d_in[1];
    const float* b = (const float*)d_in[2];
    float* out = (float*)d_out;

    dim3 grid_gemm((N_COLS + BN - 1) / BN, M_ROWS / BM);   // 8 x 128
    sgemm_kernel<<<grid_gemm, 256>>>(x, W, b);
    rowstats_kernel<<<M_ROWS, 128>>>();
    vote_kernel<<<NBATCH, 256>>>(out);
}

// round 3
// speedup vs baseline: 2.7353x; 2.7353x over previous
#include <cuda_runtime.h>
#include <cuda_fp16.h>
#include <cstdint>
#include <math.h>

// ---------------------------------------------------------------------------
// Problem constants
// ---------------------------------------------------------------------------
#define M_ROWS 16384
#define N_COLS 1000
#define N_PAD  1024
#define K_DIM  4096
#define NUM_TTA_ 64
#define KEPT 6          // int(0.1 * 64)
#define NBATCH 256      // 16384 / 64

#define LO_SCALE 2048.0f      // 2^11
#define LO_INV   (1.0f / 2048.0f)

// GEMM tiling
#define BM 128
#define BN 128
#define BKH 64                 // halves per k chunk (=128 bytes per row)
#define KITERS (K_DIM / BKH)   // 64

// ---------------------------------------------------------------------------
// Device-global scratch (allocation-free per harness rules)
// ---------------------------------------------------------------------------
__device__ __half g_xh[(size_t)M_ROWS * K_DIM];
__device__ __half g_xl[(size_t)M_ROWS * K_DIM];
__device__ __half g_wh[(size_t)N_PAD * K_DIM];   // W transposed, hi
__device__ __half g_wl[(size_t)N_PAD * K_DIM];   // W transposed, lo*2^11
__device__ float  g_logits[(size_t)M_ROWS * N_COLS];
__device__ float  g_ent[M_ROWS];
__device__ int    g_vote[M_ROWS];

// ---------------------------------------------------------------------------
// PTX helpers (all sm_80-level: compile for compute_103 baseline)
// ---------------------------------------------------------------------------
__device__ __forceinline__ uint32_t smem_u32(const void* p) {
    uint32_t a;
    asm("{ .reg .u64 t; cvta.to.shared.u64 t, %1; cvt.u32.u64 %0, t; }"
        : "=r"(a) : "l"(p));
    return a;
}

#define SWZ(o) ((o) ^ (((o) >> 3) & 0x70))

__device__ __forceinline__ void cp16(uint32_t saddr, const void* g) {
    asm volatile("cp.async.cg.shared.global [%0], [%1], 16;"
                 :: "r"(saddr), "l"(g) : "memory");
}

#define LDSM4(R, ADDR) \
    asm volatile("ldmatrix.sync.aligned.m8n8.x4.shared.b16 {%0,%1,%2,%3}, [%4];" \
        : "=r"((R)[0]), "=r"((R)[1]), "=r"((R)[2]), "=r"((R)[3]) : "r"(ADDR))

__device__ __forceinline__ void mma16816(float* c, const uint32_t* a,
                                         uint32_t b0, uint32_t b1) {
    asm volatile(
        "mma.sync.aligned.m16n8k16.row.col.f32.f16.f16.f32 "
        "{%0,%1,%2,%3}, {%4,%5,%6,%7}, {%8,%9}, {%0,%1,%2,%3};"
        : "+f"(c[0]), "+f"(c[1]), "+f"(c[2]), "+f"(c[3])
        : "r"(a[0]), "r"(a[1]), "r"(a[2]), "r"(a[3]), "r"(b0), "r"(b1));
}

// ---------------------------------------------------------------------------
// Pre-pass 1: split x (fp32) into fp16 hi + fp16 lo*2^11
// ---------------------------------------------------------------------------
__global__ __launch_bounds__(256)
void split_x_kernel(const float* __restrict__ x) {
    size_t i = ((size_t)blockIdx.x * 256 + threadIdx.x) * 8;
    float4 v0 = *(const float4*)(x + i);
    float4 v1 = *(const float4*)(x + i + 4);
    float f[8] = {v0.x, v0.y, v0.z, v0.w, v1.x, v1.y, v1.z, v1.w};
    __half h[8], l[8];
#pragma unroll
    for (int e = 0; e < 8; e++) {
        h[e] = __float2half_rn(f[e]);
        l[e] = __float2half_rn((f[e] - __half2float(h[e])) * LO_SCALE);
    }
    *(uint4*)(g_xh + i) = *(const uint4*)h;
    *(uint4*)(g_xl + i) = *(const uint4*)l;
}

// ---------------------------------------------------------------------------
// Pre-pass 2: transpose W [K, N] -> [N_PAD, K], split into fp16 hi/lo*2^11
// ---------------------------------------------------------------------------
__global__ __launch_bounds__(1024)
void split_wt_kernel(const float* __restrict__ W) {
    __shared__ float tile[32][33];
    const int k0 = blockIdx.x * 32;
    const int n0 = blockIdx.y * 32;
    const int tx = threadIdx.x, ty = threadIdx.y;
    const int n = n0 + tx;
    float v = (n < N_COLS) ? W[(size_t)(k0 + ty) * N_COLS + n] : 0.0f;
    tile[ty][tx] = v;
    __syncthreads();
    float u = tile[tx][ty];   // = W[k0+tx][n0+ty]
    __half h = __float2half_rn(u);
    __half l = __float2half_rn((u - __half2float(h)) * LO_SCALE);
    size_t o = (size_t)(n0 + ty) * K_DIM + k0 + tx;
    g_wh[o] = h;
    g_wl[o] = l;
}

// ---------------------------------------------------------------------------
// Kernel A: fp16x2 split GEMM via mma.sync (HMMA), cp.async double buffer.
//   logits[m][n] = sum_k x[m][k] * W[k][n] + b[n]
//   = (hi_x hi_w) + 2^-11 * (hi_x lo_w' + lo_x' hi_w)   [lo' = lo * 2^11]
// ---------------------------------------------------------------------------
// dynamic smem: 2 stages x (Ahi | Alo | Bhi | Blo), each 128x64 half = 16KB
#define STG_BYTES 65536
#define SMEM_BYTES (2 * STG_BYTES + 1024)

__global__ __launch_bounds__(256, 1)
void gemm_fp16x2_kernel(const float* __restrict__ bias) {
    extern __shared__ char smem_raw[];
    uint32_t sbase = smem_u32(smem_raw);
    sbase = (sbase + 1023u) & ~1023u;

    const int tid  = threadIdx.x;
    const int lane = tid & 31;
    const int wid  = tid >> 5;
    const int wm   = wid & 3;    // warp m index (0..3) -> 32 rows each
    const int wn   = wid >> 2;   // warp n index (0..1) -> 64 cols each
    const int m0 = blockIdx.y * BM;
    const int n0 = blockIdx.x * BN;

    // Loader mapping: row = tid>>1 (0..127), half-row = tid&1 (4 x 16B chunks)
    const int lrow = tid >> 1;
    const int lcb  = (tid & 1) * 64;          // byte offset within 128B row
    const __half* gAh = g_xh + (size_t)(m0 + lrow) * K_DIM + (lcb >> 1);
    const __half* gAl = g_xl + (size_t)(m0 + lrow) * K_DIM + (lcb >> 1);
    const __half* gBh = g_wh + (size_t)(n0 + lrow) * K_DIM + (lcb >> 1);
    const __half* gBl = g_wl + (size_t)(n0 + lrow) * K_DIM + (lcb >> 1);

    uint32_t soff[4];
#pragma unroll
    for (int j = 0; j < 4; j++)
        soff[j] = SWZ((uint32_t)(lrow * 128 + lcb + j * 16));

    float ch[2][8][4];   // hi*hi accumulators
    float cl[2][8][4];   // (hi*lo' + lo'*hi) accumulators (scale 2^11)
#pragma unroll
    for (int mt = 0; mt < 2; mt++)
#pragma unroll
        for (int n8 = 0; n8 < 8; n8++)
#pragma unroll
            for (int j = 0; j < 4; j++) { ch[mt][n8][j] = 0.f; cl[mt][n8][j] = 0.f; }

    // --- pipeline prologue: stage 0 ---
    {
        uint32_t s = sbase;
#pragma unroll
        for (int j = 0; j < 4; j++) {
            cp16(s + 0     + soff[j], gAh + j * 8);
            cp16(s + 16384 + soff[j], gAl + j * 8);
            cp16(s + 32768 + soff[j], gBh + j * 8);
            cp16(s + 49152 + soff[j], gBl + j * 8);
        }
        asm volatile("cp.async.commit_group;" ::: "memory");
    }

    for (int it = 0; it < KITERS; it++) {
        const int buf = it & 1;
        if (it + 1 < KITERS) {
            uint32_t s = sbase + (buf ^ 1) * STG_BYTES;
            const int kh = (it + 1) * BKH;
#pragma unroll
            for (int j = 0; j < 4; j++) {
                cp16(s + 0     + soff[j], gAh + kh + j * 8);
                cp16(s + 16384 + soff[j], gAl + kh + j * 8);
                cp16(s + 32768 + soff[j], gBh + kh + j * 8);
                cp16(s + 49152 + soff[j], gBl + kh + j * 8);
            }
            asm volatile("cp.async.commit_group;" ::: "memory");
            asm volatile("cp.async.wait_group 1;" ::: "memory");
        } else {
            asm volatile("cp.async.wait_group 0;" ::: "memory");
        }
        __syncthreads();

        const uint32_t sA  = sbase + buf * STG_BYTES;
        const uint32_t sAl = sA + 16384;
        const uint32_t sB  = sA + 32768;
        const uint32_t sBl = sA + 49152;

#pragma unroll
        for (int ks = 0; ks < 4; ks++) {
            const uint32_t chunkb = ks * 32 + ((lane >> 4) << 4);
            uint32_t ah[2][4], al[2][4];
#pragma unroll
            for (int mt = 0; mt < 2; mt++) {
                uint32_t off = SWZ((uint32_t)((wm * 32 + mt * 16 + (lane & 15)) * 128) + chunkb);
                LDSM4(ah[mt], sA + off);
                LDSM4(al[mt], sAl + off);
            }
#pragma unroll
            for (int nt = 0; nt < 4; nt++) {
                uint32_t off = SWZ((uint32_t)((wn * 64 + nt * 16 + (lane & 15)) * 128) + chunkb);
                uint32_t bh[4], bl[4];
                LDSM4(bh, sB + off);
                LDSM4(bl, sBl + off);
#pragma unroll
                for (int mt = 0; mt < 2; mt++) {
#pragma unroll
                    for (int h2 = 0; h2 < 2; h2++) {
                        const int n8 = nt * 2 + h2;
                        mma16816(ch[mt][n8], ah[mt], bh[h2], bh[h2 + 2]);
                        mma16816(cl[mt][n8], ah[mt], bl[h2], bl[h2 + 2]);
                        mma16816(cl[mt][n8], al[mt], bh[h2], bh[h2 + 2]);
                    }
                }
            }
        }
        __syncthreads();
    }

    // --- epilogue: combine, add bias, store ---
#pragma unroll
    for (int mt = 0; mt < 2; mt++) {
        const int rbase = m0 + wm * 32 + mt * 16 + (lane >> 2);
#pragma unroll
        for (int n8 = 0; n8 < 8; n8++) {
            const int col = n0 + wn * 64 + n8 * 8 + (lane & 3) * 2;
            if (col < N_COLS) {
                float2 bv = *(const float2*)(bias + col);
                float2 o0, o1;
                o0.x = ch[mt][n8][0] + cl[mt][n8][0] * LO_INV + bv.x;
                o0.y = ch[mt][n8][1] + cl[mt][n8][1] * LO_INV + bv.y;
                o1.x = ch[mt][n8][2] + cl[mt][n8][2] * LO_INV + bv.x;
                o1.y = ch[mt][n8][3] + cl[mt][n8][3] * LO_INV + bv.y;
                *(float2*)(g_logits + (size_t)rbase * N_COLS + col) = o0;
                *(float2*)(g_logits + (size_t)(rbase + 8) * N_COLS + col) = o1;
            }
        }
    }
}

// ---------------------------------------------------------------------------
// Kernel B: per-row argmax (first-index tie-break) + softmax entropy
// ---------------------------------------------------------------------------
__global__ __launch_bounds__(128)
void rowstats_kernel() {
    const int row = blockIdx.x;
    const float* z = g_logits + (size_t)row * N_COLS;
    const int tid = threadIdx.x;

    __shared__ float smx[128];
    __shared__ int smi[128];
    __shared__ float sS[128];
    __shared__ float sT[128];

    float mx = -3.4e38f;
    int mi = 0x7fffffff;
    for (int c = tid; c < N_COLS; c += 128) {
        float v = z[c];
        if (v > mx) { mx = v; mi = c; }
    }
    smx[tid] = mx; smi[tid] = mi;
    __syncthreads();
    for (int s = 64; s > 0; s >>= 1) {
        if (tid < s) {
            float vo = smx[tid + s]; int io = smi[tid + s];
            if (vo > smx[tid] || (vo == smx[tid] && io < smi[tid])) {
                smx[tid] = vo; smi[tid] = io;
            }
        }
        __syncthreads();
    }
    const float m = smx[0];
    const int vote = smi[0];
    __syncthreads();

    float S = 0.f, T = 0.f;
    for (int c = tid; c < N_COLS; c += 128) {
        float u = z[c] - m;
        float e = expf(u);
        S += e;
        T += u * e;
    }
    sS[tid] = S; sT[tid] = T;
    __syncthreads();
    for (int s = 64; s > 0; s >>= 1) {
        if (tid < s) { sS[tid] += sS[tid + s]; sT[tid] += sT[tid + s]; }
        __syncthreads();
    }
    if (tid == 0) {
        g_ent[row] = logf(sS[0]) - sT[0] / sS[0];
        g_vote[row] = vote;
    }
}

// ---------------------------------------------------------------------------
// Kernel C: per-batch voting
// ---------------------------------------------------------------------------
__global__ __launch_bounds__(256)
void vote_kernel(float* __restrict__ out) {
    __shared__ float ent_s[NUM_TTA_];
    __shared__ int sv[NUM_TTA_];
    __shared__ int counts[N_COLS];
    __shared__ int rmx[256];
    __shared__ int rcnt[256];

    const int b = blockIdx.x;
    const int tid = threadIdx.x;

    if (tid < NUM_TTA_) ent_s[tid] = g_ent[b * NUM_TTA_ + tid];
    for (int c = tid; c < N_COLS; c += 256) counts[c] = 0;
    __syncthreads();

    if (tid < NUM_TTA_) {
        float e = ent_s[tid];
        int r = 0;
#pragma unroll
        for (int j = 0; j < NUM_TTA_; j++) {
            float ej = ent_s[j];
            r += (ej < e) || (ej == e && j < tid);
        }
        sv[r] = g_vote[b * NUM_TTA_ + tid];
    }
    __syncthreads();

    if (tid == 0) {
        for (int i = 0; i < KEPT; i++) counts[sv[i]]++;
    }
    __syncthreads();

    for (int i = 0; i < NUM_TTA_ - KEPT; i++) {
        int mx = -1, cnt = 0;
        for (int c = tid; c < N_COLS; c += 256) {
            int v = counts[c];
            if (v > mx) { mx = v; cnt = 1; }
            else if (v == mx) cnt++;
        }
        rmx[tid] = mx; rcnt[tid] = cnt;
        __syncthreads();
        for (int s = 128; s > 0; s >>= 1) {
            if (tid < s) {
                if (rmx[tid + s] > rmx[tid]) { rmx[tid] = rmx[tid + s]; rcnt[tid] = rcnt[tid + s]; }
                else if (rmx[tid + s] == rmx[tid]) rcnt[tid] += rcnt[tid + s];
            }
            __syncthreads();
        }
        if (tid == 0 && rcnt[0] > 1) counts[sv[KEPT + i]] += 1;
        __syncthreads();
    }

    for (int c = tid; c < N_COLS; c += 256) {
        out[(size_t)b * N_COLS + c] = logf((float)counts[c] * (1.0f / 64.0f) + 1e-8f);
    }
}

// ---------------------------------------------------------------------------
extern "C" void kernel_launch(void* const* d_in, const int* in_sizes, int n_in,
                              void* d_out, int out_size) {
    const float* x = (const float*)d_in[0];
    const float* W = (const float*)d_in[1];
    const float* b = (const float*)d_in[2];
    float* out = (float*)d_out;

    cudaFuncSetAttribute(gemm_fp16x2_kernel,
                         cudaFuncAttributeMaxDynamicSharedMemorySize, SMEM_BYTES);

    split_x_kernel<<<(M_ROWS * (size_t)K_DIM) / 8 / 256, 256>>>(x);
    split_wt_kernel<<<dim3(K_DIM / 32, N_PAD / 32), dim3(32, 32)>>>(W);

    gemm_fp16x2_kernel<<<dim3(N_PAD / BN, M_ROWS / BM), 256, SMEM_BYTES>>>(b);

    rowstats_kernel<<<M_ROWS, 128>>>();
    vote_kernel<<<NBATCH, 256>>>(out);
}

// round 4
// speedup vs baseline: 3.2127x; 1.1745x over previous
#include <cuda_runtime.h>
#include <cuda_fp16.h>
#include <cstdint>
#include <math.h>

// ---------------------------------------------------------------------------
// Problem constants
// ---------------------------------------------------------------------------
#define M_ROWS 16384
#define N_COLS 1000
#define N_PAD  1024
#define K_DIM  4096
#define NUM_TTA_ 64
#define KEPT 6
#define NBATCH 256

#define LO_SCALE 2048.0f      // 2^11
#define LO_INV   (1.0f / 2048.0f)

// GEMM tiling: 128x128 CTA tile, 16 warps (4x4), warp tile 32x32
#define BM 128
#define BN 128
#define BKH 64                 // halves per k chunk (=128 bytes per row)
#define KITERS (K_DIM / BKH)   // 64
#define NSTAGE 3
#define STG_BYTES 65536        // 4 arrays x 128 rows x 128 B

// ---------------------------------------------------------------------------
// Device-global scratch
// ---------------------------------------------------------------------------
__device__ __half g_xh[(size_t)M_ROWS * K_DIM];
__device__ __half g_xl[(size_t)M_ROWS * K_DIM];
__device__ __half g_wh[(size_t)N_PAD * K_DIM];
__device__ __half g_wl[(size_t)N_PAD * K_DIM];
__device__ float  g_logits[(size_t)M_ROWS * N_COLS];
__device__ float  g_ent[M_ROWS];
__device__ int    g_vote[M_ROWS];

// ---------------------------------------------------------------------------
// PTX helpers (sm_80-level, compile under compute_103 baseline PTX)
// ---------------------------------------------------------------------------
__device__ __forceinline__ uint32_t smem_u32(const void* p) {
    uint32_t a;
    asm("{ .reg .u64 t; cvta.to.shared.u64 t, %1; cvt.u32.u64 %0, t; }"
        : "=r"(a) : "l"(p));
    return a;
}

#define SWZ(o) ((o) ^ (((o) >> 3) & 0x70))

__device__ __forceinline__ void cp16(uint32_t saddr, const void* g) {
    asm volatile("cp.async.cg.shared.global [%0], [%1], 16;"
                 :: "r"(saddr), "l"(g) : "memory");
}

#define LDSM4(R, ADDR) \
    asm volatile("ldmatrix.sync.aligned.m8n8.x4.shared.b16 {%0,%1,%2,%3}, [%4];" \
        : "=r"((R)[0]), "=r"((R)[1]), "=r"((R)[2]), "=r"((R)[3]) : "r"(ADDR))

__device__ __forceinline__ void mma16816(float* c, const uint32_t* a,
                                         uint32_t b0, uint32_t b1) {
    asm volatile(
        "mma.sync.aligned.m16n8k16.row.col.f32.f16.f16.f32 "
        "{%0,%1,%2,%3}, {%4,%5,%6,%7}, {%8,%9}, {%0,%1,%2,%3};"
        : "+f"(c[0]), "+f"(c[1]), "+f"(c[2]), "+f"(c[3])
        : "r"(a[0]), "r"(a[1]), "r"(a[2]), "r"(a[3]), "r"(b0), "r"(b1));
}

// ---------------------------------------------------------------------------
// Pre-pass 1: split x (fp32) -> fp16 hi + fp16 lo*2^11
// ---------------------------------------------------------------------------
__global__ __launch_bounds__(256)
void split_x_kernel(const float* __restrict__ x) {
    size_t i = ((size_t)blockIdx.x * 256 + threadIdx.x) * 8;
    float4 v0 = *(const float4*)(x + i);
    float4 v1 = *(const float4*)(x + i + 4);
    float f[8] = {v0.x, v0.y, v0.z, v0.w, v1.x, v1.y, v1.z, v1.w};
    __half h[8], l[8];
#pragma unroll
    for (int e = 0; e < 8; e++) {
        h[e] = __float2half_rn(f[e]);
        l[e] = __float2half_rn((f[e] - __half2float(h[e])) * LO_SCALE);
    }
    *(uint4*)(g_xh + i) = *(const uint4*)h;
    *(uint4*)(g_xl + i) = *(const uint4*)l;
}

// ---------------------------------------------------------------------------
// Pre-pass 2: transpose W [K, N] -> [N_PAD, K], split fp16 hi/lo*2^11
// ---------------------------------------------------------------------------
__global__ __launch_bounds__(1024)
void split_wt_kernel(const float* __restrict__ W) {
    __shared__ float tile[32][33];
    const int k0 = blockIdx.x * 32;
    const int n0 = blockIdx.y * 32;
    const int tx = threadIdx.x, ty = threadIdx.y;
    const int n = n0 + tx;
    float v = (n < N_COLS) ? W[(size_t)(k0 + ty) * N_COLS + n] : 0.0f;
    tile[ty][tx] = v;
    __syncthreads();
    float u = tile[tx][ty];
    __half h = __float2half_rn(u);
    __half l = __float2half_rn((u - __half2float(h)) * LO_SCALE);
    size_t o = (size_t)(n0 + ty) * K_DIM + k0 + tx;
    g_wh[o] = h;
    g_wl[o] = l;
}

// ---------------------------------------------------------------------------
// Kernel A: fp16x2 split GEMM, 512 threads, 3-stage cp.async pipeline.
// ---------------------------------------------------------------------------
#define SMEM_BYTES (NSTAGE * STG_BYTES + 1024)

__global__ __launch_bounds__(512, 1)
void gemm_fp16x2_kernel(const float* __restrict__ bias) {
    extern __shared__ char smem_raw[];
    uint32_t sbase = smem_u32(smem_raw);
    sbase = (sbase + 1023u) & ~1023u;

    const int tid  = threadIdx.x;
    const int lane = tid & 31;
    const int wid  = tid >> 5;
    const int wm   = wid & 3;    // 4 warp rows -> 32 M-rows each
    const int wn   = wid >> 2;   // 4 warp cols -> 32 N-cols each
    const int m0 = blockIdx.y * BM;
    const int n0 = blockIdx.x * BN;

    // Loader: row = tid>>2 (0..127), 2 chunks per array at bytes c*16, c*16+64
    const int lrow = tid >> 2;
    const int lcb  = (tid & 3) * 16;
    const __half* gAh = g_xh + (size_t)(m0 + lrow) * K_DIM + (lcb >> 1);
    const __half* gAl = g_xl + (size_t)(m0 + lrow) * K_DIM + (lcb >> 1);
    const __half* gBh = g_wh + (size_t)(n0 + lrow) * K_DIM + (lcb >> 1);
    const __half* gBl = g_wl + (size_t)(n0 + lrow) * K_DIM + (lcb >> 1);

    const uint32_t so0 = SWZ((uint32_t)(lrow * 128 + lcb));
    const uint32_t so1 = SWZ((uint32_t)(lrow * 128 + lcb + 64));

    float ch[2][4][4];   // hi*hi
    float cl[2][4][4];   // hi*lo' + lo'*hi   (scale 2^11)
#pragma unroll
    for (int mt = 0; mt < 2; mt++)
#pragma unroll
        for (int n8 = 0; n8 < 4; n8++)
#pragma unroll
            for (int j = 0; j < 4; j++) { ch[mt][n8][j] = 0.f; cl[mt][n8][j] = 0.f; }

    // prologue: stages 0, 1
#pragma unroll
    for (int s = 0; s < 2; s++) {
        const uint32_t sb = sbase + s * STG_BYTES;
        const int kh = s * BKH + (lcb >> 1);
        cp16(sb + 0     + so0, gAh + s * BKH);       cp16(sb + 0     + so1, gAh + s * BKH + 32);
        cp16(sb + 16384 + so0, gAl + s * BKH);       cp16(sb + 16384 + so1, gAl + s * BKH + 32);
        cp16(sb + 32768 + so0, gBh + s * BKH);       cp16(sb + 32768 + so1, gBh + s * BKH + 32);
        cp16(sb + 49152 + so0, gBl + s * BKH);       cp16(sb + 49152 + so1, gBl + s * BKH + 32);
        asm volatile("cp.async.commit_group;" ::: "memory");
        (void)kh;
    }

    for (int it = 0; it < KITERS; it++) {
        // wait for stage `it`
        if (it < KITERS - 1) {
            asm volatile("cp.async.wait_group 1;" ::: "memory");
        } else {
            asm volatile("cp.async.wait_group 0;" ::: "memory");
        }
        __syncthreads();

        // issue loads for stage it+2 (slot freed by stage it-1)
        if (it + 2 < KITERS) {
            const uint32_t sb = sbase + ((it + 2) % NSTAGE) * STG_BYTES;
            const int kh = (it + 2) * BKH;
            cp16(sb + 0     + so0, gAh + kh);        cp16(sb + 0     + so1, gAh + kh + 32);
            cp16(sb + 16384 + so0, gAl + kh);        cp16(sb + 16384 + so1, gAl + kh + 32);
            cp16(sb + 32768 + so0, gBh + kh);        cp16(sb + 32768 + so1, gBh + kh + 32);
            cp16(sb + 49152 + so0, gBl + kh);        cp16(sb + 49152 + so1, gBl + kh + 32);
            asm volatile("cp.async.commit_group;" ::: "memory");
        }

        const uint32_t sA  = sbase + (it % NSTAGE) * STG_BYTES;
        const uint32_t sAl = sA + 16384;
        const uint32_t sB  = sA + 32768;
        const uint32_t sBl = sA + 49152;

#pragma unroll
        for (int ks = 0; ks < 4; ks++) {
            const uint32_t chunkb = ks * 32 + ((lane >> 4) << 4);
            uint32_t ah[2][4], al[2][4];
#pragma unroll
            for (int mt = 0; mt < 2; mt++) {
                uint32_t off = SWZ((uint32_t)((wm * 32 + mt * 16 + (lane & 15)) * 128) + chunkb);
                LDSM4(ah[mt], sA + off);
                LDSM4(al[mt], sAl + off);
            }
#pragma unroll
            for (int nt = 0; nt < 2; nt++) {
                uint32_t off = SWZ((uint32_t)((wn * 32 + nt * 16 + (lane & 15)) * 128) + chunkb);
                uint32_t bh[4], bl[4];
                LDSM4(bh, sB + off);
                LDSM4(bl, sBl + off);
#pragma unroll
                for (int mt = 0; mt < 2; mt++) {
#pragma unroll
                    for (int h2 = 0; h2 < 2; h2++) {
                        const int n8 = nt * 2 + h2;
                        mma16816(ch[mt][n8], ah[mt], bh[h2], bh[h2 + 2]);
                        mma16816(cl[mt][n8], ah[mt], bl[h2], bl[h2 + 2]);
                        mma16816(cl[mt][n8], al[mt], bh[h2], bh[h2 + 2]);
                    }
                }
            }
        }
        __syncthreads();
    }

    // epilogue: combine hi + lo/2^11, add bias, store
#pragma unroll
    for (int mt = 0; mt < 2; mt++) {
        const int rbase = m0 + wm * 32 + mt * 16 + (lane >> 2);
#pragma unroll
        for (int n8 = 0; n8 < 4; n8++) {
            const int col = n0 + wn * 32 + n8 * 8 + (lane & 3) * 2;
            if (col < N_COLS) {
                float2 bv = *(const float2*)(bias + col);
                float2 o0, o1;
                o0.x = ch[mt][n8][0] + cl[mt][n8][0] * LO_INV + bv.x;
                o0.y = ch[mt][n8][1] + cl[mt][n8][1] * LO_INV + bv.y;
                o1.x = ch[mt][n8][2] + cl[mt][n8][2] * LO_INV + bv.x;
                o1.y = ch[mt][n8][3] + cl[mt][n8][3] * LO_INV + bv.y;
                *(float2*)(g_logits + (size_t)rbase * N_COLS + col) = o0;
                *(float2*)(g_logits + (size_t)(rbase + 8) * N_COLS + col) = o1;
            }
        }
    }
}

// ---------------------------------------------------------------------------
// Kernel B: per-row argmax + softmax entropy
// ---------------------------------------------------------------------------
__global__ __launch_bounds__(128)
void rowstats_kernel() {
    const int row = blockIdx.x;
    const float* z = g_logits + (size_t)row * N_COLS;
    const int tid = threadIdx.x;

    __shared__ float smx[128];
    __shared__ int smi[128];
    __shared__ float sS[128];
    __shared__ float sT[128];

    float mx = -3.4e38f;
    int mi = 0x7fffffff;
    for (int c = tid; c < N_COLS; c += 128) {
        float v = z[c];
        if (v > mx) { mx = v; mi = c; }
    }
    smx[tid] = mx; smi[tid] = mi;
    __syncthreads();
    for (int s = 64; s > 0; s >>= 1) {
        if (tid < s) {
            float vo = smx[tid + s]; int io = smi[tid + s];
            if (vo > smx[tid] || (vo == smx[tid] && io < smi[tid])) {
                smx[tid] = vo; smi[tid] = io;
            }
        }
        __syncthreads();
    }
    const float m = smx[0];
    const int vote = smi[0];
    __syncthreads();

    float S = 0.f, T = 0.f;
    for (int c = tid; c < N_COLS; c += 128) {
        float u = z[c] - m;
        float e = expf(u);
        S += e;
        T += u * e;
    }
    sS[tid] = S; sT[tid] = T;
    __syncthreads();
    for (int s = 64; s > 0; s >>= 1) {
        if (tid < s) { sS[tid] += sS[tid + s]; sT[tid] += sT[tid + s]; }
        __syncthreads();
    }
    if (tid == 0) {
        g_ent[row] = logf(sS[0]) - sT[0] / sS[0];
        g_vote[row] = vote;
    }
}

// ---------------------------------------------------------------------------
// Kernel C: per-batch voting
// ---------------------------------------------------------------------------
__global__ __launch_bounds__(256)
void vote_kernel(float* __restrict__ out) {
    __shared__ float ent_s[NUM_TTA_];
    __shared__ int sv[NUM_TTA_];
    __shared__ int counts[N_COLS];
    __shared__ int rmx[256];
    __shared__ int rcnt[256];

    const int b = blockIdx.x;
    const int tid = threadIdx.x;

    if (tid < NUM_TTA_) ent_s[tid] = g_ent[b * NUM_TTA_ + tid];
    for (int c = tid; c < N_COLS; c += 256) counts[c] = 0;
    __syncthreads();

    if (tid < NUM_TTA_) {
        float e = ent_s[tid];
        int r = 0;
#pragma unroll
        for (int j = 0; j < NUM_TTA_; j++) {
            float ej = ent_s[j];
            r += (ej < e) || (ej == e && j < tid);
        }
        sv[r] = g_vote[b * NUM_TTA_ + tid];
    }
    __syncthreads();

    if (tid == 0) {
        for (int i = 0; i < KEPT; i++) counts[sv[i]]++;
    }
    __syncthreads();

    for (int i = 0; i < NUM_TTA_ - KEPT; i++) {
        int mx = -1, cnt = 0;
        for (int c = tid; c < N_COLS; c += 256) {
            int v = counts[c];
            if (v > mx) { mx = v; cnt = 1; }
            else if (v == mx) cnt++;
        }
        rmx[tid] = mx; rcnt[tid] = cnt;
        __syncthreads();
        for (int s = 128; s > 0; s >>= 1) {
            if (tid < s) {
                if (rmx[tid + s] > rmx[tid]) { rmx[tid] = rmx[tid + s]; rcnt[tid] = rcnt[tid + s]; }
                else if (rmx[tid + s] == rmx[tid]) rcnt[tid] += rcnt[tid + s];
            }
            __syncthreads();
        }
        if (tid == 0 && rcnt[0] > 1) counts[sv[KEPT + i]] += 1;
        __syncthreads();
    }

    for (int c = tid; c < N_COLS; c += 256) {
        out[(size_t)b * N_COLS + c] = logf((float)counts[c] * (1.0f / 64.0f) + 1e-8f);
    }
}

// ---------------------------------------------------------------------------
extern "C" void kernel_launch(void* const* d_in, const int* in_sizes, int n_in,
                              void* d_out, int out_size) {
    const float* x = (const float*)d_in[0];
    const float* W = (const float*)d_in[1];
    const float* b = (const float*)d_in[2];
    float* out = (float*)d_out;

    cudaFuncSetAttribute(gemm_fp16x2_kernel,
                         cudaFuncAttributeMaxDynamicSharedMemorySize, SMEM_BYTES);

    split_x_kernel<<<(M_ROWS * (size_t)K_DIM) / 8 / 256, 256>>>(x);
    split_wt_kernel<<<dim3(K_DIM / 32, N_PAD / 32), dim3(32, 32)>>>(W);

    // grid.x = N dim fastest: CTAs sharing an A-tile run concurrently -> A served from L2
    gemm_fp16x2_kernel<<<dim3(N_PAD / BN, M_ROWS / BM), 512, SMEM_BYTES>>>(b);

    rowstats_kernel<<<M_ROWS, 128>>>();
    vote_kernel<<<NBATCH, 256>>>(out);
}

// round 5
// speedup vs baseline: 3.2290x; 1.0051x over previous
#include <cuda_runtime.h>
#include <cuda_fp16.h>
#include <cstdint>
#include <math.h>

// ---------------------------------------------------------------------------
// Problem constants
// ---------------------------------------------------------------------------
#define M_ROWS 16384
#define N_COLS 1000
#define N_PAD  1024
#define K_DIM  4096
#define NUM_TTA_ 64
#define KEPT 6
#define NBATCH 256

// GEMM tiling: 128x128 CTA tile, 16 warps (4x4), warp tile 32x32
#define BM 128
#define BN 128
#define BKH 64                 // halves per k chunk (=128 bytes per row)
#define KITERS (K_DIM / BKH)   // 64
#define NSTAGE 3
#define STG_BYTES 65536        // 4 arrays x 128 rows x 128 B

// ---------------------------------------------------------------------------
// Device-global scratch
// ---------------------------------------------------------------------------
__device__ __half g_xh[(size_t)M_ROWS * K_DIM];
__device__ __half g_xl[(size_t)M_ROWS * K_DIM];   // UNscaled residual
__device__ __half g_wh[(size_t)N_PAD * K_DIM];
__device__ __half g_wl[(size_t)N_PAD * K_DIM];    // UNscaled residual
__device__ float  g_logits[(size_t)M_ROWS * N_COLS];
__device__ float  g_ent[M_ROWS];
__device__ int    g_vote[M_ROWS];

// ---------------------------------------------------------------------------
// PTX helpers (sm_80-level, compile under compute_103 baseline PTX)
// ---------------------------------------------------------------------------
__device__ __forceinline__ uint32_t smem_u32(const void* p) {
    uint32_t a;
    asm("{ .reg .u64 t; cvta.to.shared.u64 t, %1; cvt.u32.u64 %0, t; }"
        : "=r"(a) : "l"(p));
    return a;
}

#define SWZ(o) ((o) ^ (((o) >> 3) & 0x70))

__device__ __forceinline__ void cp16(uint32_t saddr, const void* g) {
    asm volatile("cp.async.cg.shared.global [%0], [%1], 16;"
                 :: "r"(saddr), "l"(g) : "memory");
}

#define LDSM4(R, ADDR) \
    asm volatile("ldmatrix.sync.aligned.m8n8.x4.shared.b16 {%0,%1,%2,%3}, [%4];" \
        : "=r"((R)[0]), "=r"((R)[1]), "=r"((R)[2]), "=r"((R)[3]) : "r"(ADDR))

__device__ __forceinline__ void mma16816(float* c, const uint32_t* a,
                                         uint32_t b0, uint32_t b1) {
    asm volatile(
        "mma.sync.aligned.m16n8k16.row.col.f32.f16.f16.f32 "
        "{%0,%1,%2,%3}, {%4,%5,%6,%7}, {%8,%9}, {%0,%1,%2,%3};"
        : "+f"(c[0]), "+f"(c[1]), "+f"(c[2]), "+f"(c[3])
        : "r"(a[0]), "r"(a[1]), "r"(a[2]), "r"(a[3]), "r"(b0), "r"(b1));
}

// ---------------------------------------------------------------------------
// Pre-pass 1: split x (fp32) -> fp16 hi + fp16 lo (unscaled residual)
// ---------------------------------------------------------------------------
__global__ __launch_bounds__(256)
void split_x_kernel(const float* __restrict__ x) {
    size_t i = ((size_t)blockIdx.x * 256 + threadIdx.x) * 8;
    float4 v0 = *(const float4*)(x + i);
    float4 v1 = *(const float4*)(x + i + 4);
    float f[8] = {v0.x, v0.y, v0.z, v0.w, v1.x, v1.y, v1.z, v1.w};
    __half h[8], l[8];
#pragma unroll
    for (int e = 0; e < 8; e++) {
        h[e] = __float2half_rn(f[e]);
        l[e] = __float2half_rn(f[e] - __half2float(h[e]));
    }
    *(uint4*)(g_xh + i) = *(const uint4*)h;
    *(uint4*)(g_xl + i) = *(const uint4*)l;
}

// ---------------------------------------------------------------------------
// Pre-pass 2: transpose W [K, N] -> [N_PAD, K], split fp16 hi + lo (unscaled)
// ---------------------------------------------------------------------------
__global__ __launch_bounds__(1024)
void split_wt_kernel(const float* __restrict__ W) {
    __shared__ float tile[32][33];
    const int k0 = blockIdx.x * 32;
    const int n0 = blockIdx.y * 32;
    const int tx = threadIdx.x, ty = threadIdx.y;
    const int n = n0 + tx;
    float v = (n < N_COLS) ? W[(size_t)(k0 + ty) * N_COLS + n] : 0.0f;
    tile[ty][tx] = v;
    __syncthreads();
    float u = tile[tx][ty];
    __half h = __float2half_rn(u);
    __half l = __float2half_rn(u - __half2float(h));
    size_t o = (size_t)(n0 + ty) * K_DIM + k0 + tx;
    g_wh[o] = h;
    g_wl[o] = l;
}

// ---------------------------------------------------------------------------
// Kernel A: fp16x2 split GEMM, single fp32 accumulator, 512 threads,
// 3-stage cp.async pipeline, one barrier per k-iter.
// ---------------------------------------------------------------------------
#define SMEM_BYTES (NSTAGE * STG_BYTES + 1024)

__global__ __launch_bounds__(512, 1)
void gemm_fp16x2_kernel(const float* __restrict__ bias) {
    extern __shared__ char smem_raw[];
    uint32_t sbase = smem_u32(smem_raw);
    sbase = (sbase + 1023u) & ~1023u;

    const int tid  = threadIdx.x;
    const int lane = tid & 31;
    const int wid  = tid >> 5;
    const int wm   = wid & 3;    // 4 warp rows -> 32 M-rows each
    const int wn   = wid >> 2;   // 4 warp cols -> 32 N-cols each
    const int m0 = blockIdx.y * BM;
    const int n0 = blockIdx.x * BN;

    // Loader: row = tid>>2 (0..127), 2 x 16B chunks per array
    const int lrow = tid >> 2;
    const int lcb  = (tid & 3) * 16;
    const __half* gAh = g_xh + (size_t)(m0 + lrow) * K_DIM + (lcb >> 1);
    const __half* gAl = g_xl + (size_t)(m0 + lrow) * K_DIM + (lcb >> 1);
    const __half* gBh = g_wh + (size_t)(n0 + lrow) * K_DIM + (lcb >> 1);
    const __half* gBl = g_wl + (size_t)(n0 + lrow) * K_DIM + (lcb >> 1);

    const uint32_t so0 = SWZ((uint32_t)(lrow * 128 + lcb));
    const uint32_t so1 = SWZ((uint32_t)(lrow * 128 + lcb + 64));

    float cc[2][4][4];   // single accumulator set
#pragma unroll
    for (int mt = 0; mt < 2; mt++)
#pragma unroll
        for (int n8 = 0; n8 < 4; n8++)
#pragma unroll
            for (int j = 0; j < 4; j++) cc[mt][n8][j] = 0.f;

    // prologue: stages 0, 1
#pragma unroll
    for (int s = 0; s < 2; s++) {
        const uint32_t sb = sbase + s * STG_BYTES;
        cp16(sb + 0     + so0, gAh + s * BKH);  cp16(sb + 0     + so1, gAh + s * BKH + 32);
        cp16(sb + 16384 + so0, gAl + s * BKH);  cp16(sb + 16384 + so1, gAl + s * BKH + 32);
        cp16(sb + 32768 + so0, gBh + s * BKH);  cp16(sb + 32768 + so1, gBh + s * BKH + 32);
        cp16(sb + 49152 + so0, gBl + s * BKH);  cp16(sb + 49152 + so1, gBl + s * BKH + 32);
        asm volatile("cp.async.commit_group;" ::: "memory");
    }

    for (int it = 0; it < KITERS; it++) {
        if (it < KITERS - 1) {
            asm volatile("cp.async.wait_group 1;" ::: "memory");
        } else {
            asm volatile("cp.async.wait_group 0;" ::: "memory");
        }
        __syncthreads();   // single barrier per iter: stage `it` visible, stage it-1 reads done

        if (it + 2 < KITERS) {
            const uint32_t sb = sbase + ((it + 2) % NSTAGE) * STG_BYTES;
            const int kh = (it + 2) * BKH;
            cp16(sb + 0     + so0, gAh + kh);   cp16(sb + 0     + so1, gAh + kh + 32);
            cp16(sb + 16384 + so0, gAl + kh);   cp16(sb + 16384 + so1, gAl + kh + 32);
            cp16(sb + 32768 + so0, gBh + kh);   cp16(sb + 32768 + so1, gBh + kh + 32);
            cp16(sb + 49152 + so0, gBl + kh);   cp16(sb + 49152 + so1, gBl + kh + 32);
            asm volatile("cp.async.commit_group;" ::: "memory");
        }

        const uint32_t sA  = sbase + (it % NSTAGE) * STG_BYTES;
        const uint32_t sAl = sA + 16384;
        const uint32_t sB  = sA + 32768;
        const uint32_t sBl = sA + 49152;

#pragma unroll
        for (int ks = 0; ks < 4; ks++) {
            const uint32_t chunkb = ks * 32 + ((lane >> 4) << 4);
            uint32_t ah[2][4], al[2][4];
#pragma unroll
            for (int mt = 0; mt < 2; mt++) {
                uint32_t off = SWZ((uint32_t)((wm * 32 + mt * 16 + (lane & 15)) * 128) + chunkb);
                LDSM4(ah[mt], sA + off);
                LDSM4(al[mt], sAl + off);
            }
#pragma unroll
            for (int nt = 0; nt < 2; nt++) {
                uint32_t off = SWZ((uint32_t)((wn * 32 + nt * 16 + (lane & 15)) * 128) + chunkb);
                uint32_t bh[4], bl[4];
                LDSM4(bh, sB + off);
                LDSM4(bl, sBl + off);
#pragma unroll
                for (int mt = 0; mt < 2; mt++) {
#pragma unroll
                    for (int h2 = 0; h2 < 2; h2++) {
                        const int n8 = nt * 2 + h2;
                        mma16816(cc[mt][n8], ah[mt], bh[h2], bh[h2 + 2]);
                        mma16816(cc[mt][n8], ah[mt], bl[h2], bl[h2 + 2]);
                        mma16816(cc[mt][n8], al[mt], bh[h2], bh[h2 + 2]);
                    }
                }
            }
        }
    }

    // epilogue: add bias, store
#pragma unroll
    for (int mt = 0; mt < 2; mt++) {
        const int rbase = m0 + wm * 32 + mt * 16 + (lane >> 2);
#pragma unroll
        for (int n8 = 0; n8 < 4; n8++) {
            const int col = n0 + wn * 32 + n8 * 8 + (lane & 3) * 2;
            if (col < N_COLS) {
                float2 bv = *(const float2*)(bias + col);
                float2 o0, o1;
                o0.x = cc[mt][n8][0] + bv.x;
                o0.y = cc[mt][n8][1] + bv.y;
                o1.x = cc[mt][n8][2] + bv.x;
                o1.y = cc[mt][n8][3] + bv.y;
                *(float2*)(g_logits + (size_t)rbase * N_COLS + col) = o0;
                *(float2*)(g_logits + (size_t)(rbase + 8) * N_COLS + col) = o1;
            }
        }
    }
}

// ---------------------------------------------------------------------------
// Kernel B: per-row argmax + softmax entropy
// ---------------------------------------------------------------------------
__global__ __launch_bounds__(128)
void rowstats_kernel() {
    const int row = blockIdx.x;
    const float* z = g_logits + (size_t)row * N_COLS;
    const int tid = threadIdx.x;

    __shared__ float smx[128];
    __shared__ int smi[128];
    __shared__ float sS[128];
    __shared__ float sT[128];

    float mx = -3.4e38f;
    int mi = 0x7fffffff;
    for (int c = tid; c < N_COLS; c += 128) {
        float v = z[c];
        if (v > mx) { mx = v; mi = c; }
    }
    smx[tid] = mx; smi[tid] = mi;
    __syncthreads();
    for (int s = 64; s > 0; s >>= 1) {
        if (tid < s) {
            float vo = smx[tid + s]; int io = smi[tid + s];
            if (vo > smx[tid] || (vo == smx[tid] && io < smi[tid])) {
                smx[tid] = vo; smi[tid] = io;
            }
        }
        __syncthreads();
    }
    const float m = smx[0];
    const int vote = smi[0];
    __syncthreads();

    float S = 0.f, T = 0.f;
    for (int c = tid; c < N_COLS; c += 128) {
        float u = z[c] - m;
        float e = expf(u);
        S += e;
        T += u * e;
    }
    sS[tid] = S; sT[tid] = T;
    __syncthreads();
    for (int s = 64; s > 0; s >>= 1) {
        if (tid < s) { sS[tid] += sS[tid + s]; sT[tid] += sT[tid + s]; }
        __syncthreads();
    }
    if (tid == 0) {
        g_ent[row] = logf(sS[0]) - sT[0] / sS[0];
        g_vote[row] = vote;
    }
}

// ---------------------------------------------------------------------------
// Kernel C: per-batch voting
// ---------------------------------------------------------------------------
__global__ __launch_bounds__(256)
void vote_kernel(float* __restrict__ out) {
    __shared__ float ent_s[NUM_TTA_];
    __shared__ int sv[NUM_TTA_];
    __shared__ int counts[N_COLS];
    __shared__ int rmx[256];
    __shared__ int rcnt[256];

    const int b = blockIdx.x;
    const int tid = threadIdx.x;

    if (tid < NUM_TTA_) ent_s[tid] = g_ent[b * NUM_TTA_ + tid];
    for (int c = tid; c < N_COLS; c += 256) counts[c] = 0;
    __syncthreads();

    if (tid < NUM_TTA_) {
        float e = ent_s[tid];
        int r = 0;
#pragma unroll
        for (int j = 0; j < NUM_TTA_; j++) {
            float ej = ent_s[j];
            r += (ej < e) || (ej == e && j < tid);
        }
        sv[r] = g_vote[b * NUM_TTA_ + tid];
    }
    __syncthreads();

    if (tid == 0) {
        for (int i = 0; i < KEPT; i++) counts[sv[i]]++;
    }
    __syncthreads();

    for (int i = 0; i < NUM_TTA_ - KEPT; i++) {
        int mx = -1, cnt = 0;
        for (int c = tid; c < N_COLS; c += 256) {
            int v = counts[c];
            if (v > mx) { mx = v; cnt = 1; }
            else if (v == mx) cnt++;
        }
        rmx[tid] = mx; rcnt[tid] = cnt;
        __syncthreads();
        for (int s = 128; s > 0; s >>= 1) {
            if (tid < s) {
                if (rmx[tid + s] > rmx[tid]) { rmx[tid] = rmx[tid + s]; rcnt[tid] = rcnt[tid + s]; }
                else if (rmx[tid + s] == rmx[tid]) rcnt[tid] += rcnt[tid + s];
            }
            __syncthreads();
        }
        if (tid == 0 && rcnt[0] > 1) counts[sv[KEPT + i]] += 1;
        __syncthreads();
    }

    for (int c = tid; c < N_COLS; c += 256) {
        out[(size_t)b * N_COLS + c] = logf((float)counts[c] * (1.0f / 64.0f) + 1e-8f);
    }
}

// ---------------------------------------------------------------------------
extern "C" void kernel_launch(void* const* d_in, const int* in_sizes, int n_in,
                              void* d_out, int out_size) {
    const float* x = (const float*)d_in[0];
    const float* W = (const float*)d_in[1];
    const float* b = (const float*)d_in[2];
    float* out = (float*)d_out;

    cudaFuncSetAttribute(gemm_fp16x2_kernel,
                         cudaFuncAttributeMaxDynamicSharedMemorySize, SMEM_BYTES);

    split_x_kernel<<<(M_ROWS * (size_t)K_DIM) / 8 / 256, 256>>>(x);
    split_wt_kernel<<<dim3(K_DIM / 32, N_PAD / 32), dim3(32, 32)>>>(W);

    // grid.x = N dim fastest: CTAs sharing an A-tile run concurrently -> A served from L2
    gemm_fp16x2_kernel<<<dim3(N_PAD / BN, M_ROWS / BM), 512, SMEM_BYTES>>>(b);

    rowstats_kernel<<<M_ROWS, 128>>>();
    vote_kernel<<<NBATCH, 256>>>(out);
}

// round 6
// speedup vs baseline: 3.3362x; 1.0332x over previous
#include <cuda_runtime.h>
#include <cuda_fp16.h>
#include <cstdint>
#include <math.h>

// ---------------------------------------------------------------------------
// Problem constants
// ---------------------------------------------------------------------------
#define M_ROWS 16384
#define N_COLS 1000
#define N_PAD  1024
#define K_DIM  4096
#define NUM_TTA_ 64
#define KEPT 6
#define NBATCH 256

// GEMM tiling: 128x128 CTA tile, 8 warps (4m x 2n), warp tile 32x64
// BKH=32 halves per k chunk (64 B rows, SW64 swizzle), 3-stage pipeline,
// 96KB smem/CTA -> 2 CTAs per SM.
#define BM 128
#define BN 128
#define BKH 32
#define KITERS (K_DIM / BKH)   // 128
#define NSTAGE 3
#define ARR_BYTES 8192         // 128 rows x 64 B
#define STG_BYTES (4 * ARR_BYTES)   // Ahi|Alo|Bhi|Blo = 32 KB

// ---------------------------------------------------------------------------
// Device-global scratch
// ---------------------------------------------------------------------------
__device__ __half g_xh[(size_t)M_ROWS * K_DIM];
__device__ __half g_xl[(size_t)M_ROWS * K_DIM];
__device__ __half g_wh[(size_t)N_PAD * K_DIM];
__device__ __half g_wl[(size_t)N_PAD * K_DIM];
__device__ float  g_logits[(size_t)M_ROWS * N_COLS];
__device__ float  g_ent[M_ROWS];
__device__ int    g_vote[M_ROWS];

// ---------------------------------------------------------------------------
// PTX helpers
// ---------------------------------------------------------------------------
__device__ __forceinline__ uint32_t smem_u32(const void* p) {
    uint32_t a;
    asm("{ .reg .u64 t; cvta.to.shared.u64 t, %1; cvt.u32.u64 %0, t; }"
        : "=r"(a) : "l"(p));
    return a;
}

// SW64 swizzle: conflict-free ldmatrix on 64B rows (bits [8:7] -> [5:4])
#define SWZ64(o) ((o) ^ (((o) >> 3) & 0x30))

__device__ __forceinline__ void cp16(uint32_t saddr, const void* g) {
    asm volatile("cp.async.cg.shared.global [%0], [%1], 16;"
                 :: "r"(saddr), "l"(g) : "memory");
}

#define LDSM4(R, ADDR) \
    asm volatile("ldmatrix.sync.aligned.m8n8.x4.shared.b16 {%0,%1,%2,%3}, [%4];" \
        : "=r"((R)[0]), "=r"((R)[1]), "=r"((R)[2]), "=r"((R)[3]) : "r"(ADDR))

__device__ __forceinline__ void mma16816(float* c, const uint32_t* a,
                                         uint32_t b0, uint32_t b1) {
    asm volatile(
        "mma.sync.aligned.m16n8k16.row.col.f32.f16.f16.f32 "
        "{%0,%1,%2,%3}, {%4,%5,%6,%7}, {%8,%9}, {%0,%1,%2,%3};"
        : "+f"(c[0]), "+f"(c[1]), "+f"(c[2]), "+f"(c[3])
        : "r"(a[0]), "r"(a[1]), "r"(a[2]), "r"(a[3]), "r"(b0), "r"(b1));
}

// ---------------------------------------------------------------------------
// Pre-pass 1: split x (fp32) -> fp16 hi + fp16 lo residual
// ---------------------------------------------------------------------------
__global__ __launch_bounds__(256)
void split_x_kernel(const float* __restrict__ x) {
    size_t i = ((size_t)blockIdx.x * 256 + threadIdx.x) * 8;
    float4 v0 = *(const float4*)(x + i);
    float4 v1 = *(const float4*)(x + i + 4);
    float f[8] = {v0.x, v0.y, v0.z, v0.w, v1.x, v1.y, v1.z, v1.w};
    __half h[8], l[8];
#pragma unroll
    for (int e = 0; e < 8; e++) {
        h[e] = __float2half_rn(f[e]);
        l[e] = __float2half_rn(f[e] - __half2float(h[e]));
    }
    *(uint4*)(g_xh + i) = *(const uint4*)h;
    *(uint4*)(g_xl + i) = *(const uint4*)l;
}

// ---------------------------------------------------------------------------
// Pre-pass 2: transpose W [K, N] -> [N_PAD, K], split fp16 hi + lo
// ---------------------------------------------------------------------------
__global__ __launch_bounds__(1024)
void split_wt_kernel(const float* __restrict__ W) {
    __shared__ float tile[32][33];
    const int k0 = blockIdx.x * 32;
    const int n0 = blockIdx.y * 32;
    const int tx = threadIdx.x, ty = threadIdx.y;
    const int n = n0 + tx;
    float v = (n < N_COLS) ? W[(size_t)(k0 + ty) * N_COLS + n] : 0.0f;
    tile[ty][tx] = v;
    __syncthreads();
    float u = tile[tx][ty];
    __half h = __float2half_rn(u);
    __half l = __float2half_rn(u - __half2float(h));
    size_t o = (size_t)(n0 + ty) * K_DIM + k0 + tx;
    g_wh[o] = h;
    g_wl[o] = l;
}

// ---------------------------------------------------------------------------
// Kernel A: fp16x2 split GEMM, 256 threads, 2 CTAs/SM, 3-stage pipeline
// ---------------------------------------------------------------------------
#define SMEM_BYTES (NSTAGE * STG_BYTES + 256)

__global__ __launch_bounds__(256, 2)
void gemm_fp16x2_kernel(const float* __restrict__ bias) {
    extern __shared__ char smem_raw[];
    uint32_t sbase = smem_u32(smem_raw);
    sbase = (sbase + 255u) & ~255u;

    const int tid  = threadIdx.x;
    const int lane = tid & 31;
    const int wid  = tid >> 5;
    const int wm   = wid & 3;    // 4 warp rows -> 32 M-rows each
    const int wn   = wid >> 2;   // 2 warp cols -> 64 N-cols each
    const int m0 = blockIdx.y * BM;
    const int n0 = blockIdx.x * BN;

    // Loader: 512 chunks of 16B per array; thread t handles chunks t, t+256.
    // chunk c: row = c>>2 (0..127), byte-in-row = (c&3)*16
    const int c0row = tid >> 2;
    const int c0cb  = (tid & 3) * 16;
    const int c1row = (tid + 256) >> 2;
    const int c1cb  = c0cb;
    const uint32_t sw0 = SWZ64((uint32_t)(c0row * 64 + c0cb));
    const uint32_t sw1 = SWZ64((uint32_t)(c1row * 64 + c1cb));

    const __half* gAh0 = g_xh + (size_t)(m0 + c0row) * K_DIM + (c0cb >> 1);
    const __half* gAl0 = g_xl + (size_t)(m0 + c0row) * K_DIM + (c0cb >> 1);
    const __half* gBh0 = g_wh + (size_t)(n0 + c0row) * K_DIM + (c0cb >> 1);
    const __half* gBl0 = g_wl + (size_t)(n0 + c0row) * K_DIM + (c0cb >> 1);
    const __half* gAh1 = g_xh + (size_t)(m0 + c1row) * K_DIM + (c1cb >> 1);
    const __half* gAl1 = g_xl + (size_t)(m0 + c1row) * K_DIM + (c1cb >> 1);
    const __half* gBh1 = g_wh + (size_t)(n0 + c1row) * K_DIM + (c1cb >> 1);
    const __half* gBl1 = g_wl + (size_t)(n0 + c1row) * K_DIM + (c1cb >> 1);

    float cc[2][8][4];
#pragma unroll
    for (int mt = 0; mt < 2; mt++)
#pragma unroll
        for (int n8 = 0; n8 < 8; n8++)
#pragma unroll
            for (int j = 0; j < 4; j++) cc[mt][n8][j] = 0.f;

#define LOAD_STAGE(SB, KH)                                                     \
    do {                                                                       \
        cp16((SB) + 0 * ARR_BYTES + sw0, gAh0 + (KH));                         \
        cp16((SB) + 0 * ARR_BYTES + sw1, gAh1 + (KH));                         \
        cp16((SB) + 1 * ARR_BYTES + sw0, gAl0 + (KH));                         \
        cp16((SB) + 1 * ARR_BYTES + sw1, gAl1 + (KH));                         \
        cp16((SB) + 2 * ARR_BYTES + sw0, gBh0 + (KH));                         \
        cp16((SB) + 2 * ARR_BYTES + sw1, gBh1 + (KH));                         \
        cp16((SB) + 3 * ARR_BYTES + sw0, gBl0 + (KH));                         \
        cp16((SB) + 3 * ARR_BYTES + sw1, gBl1 + (KH));                         \
        asm volatile("cp.async.commit_group;" ::: "memory");                   \
    } while (0)

    // prologue: stages 0, 1
    LOAD_STAGE(sbase, 0);
    LOAD_STAGE(sbase + STG_BYTES, BKH);

    for (int it = 0; it < KITERS; it++) {
        if (it < KITERS - 1) {
            asm volatile("cp.async.wait_group 1;" ::: "memory");
        } else {
            asm volatile("cp.async.wait_group 0;" ::: "memory");
        }
        __syncthreads();

        if (it + 2 < KITERS) {
            const uint32_t sb = sbase + ((it + 2) % NSTAGE) * STG_BYTES;
            LOAD_STAGE(sb, (it + 2) * BKH);
        }

        const uint32_t sA  = sbase + (it % NSTAGE) * STG_BYTES;
        const uint32_t sAl = sA + 1 * ARR_BYTES;
        const uint32_t sB  = sA + 2 * ARR_BYTES;
        const uint32_t sBl = sA + 3 * ARR_BYTES;

#pragma unroll
        for (int ks = 0; ks < 2; ks++) {
            const uint32_t chunkb = ks * 32 + ((lane >> 4) << 4);
            uint32_t ah[2][4], al[2][4];
#pragma unroll
            for (int mt = 0; mt < 2; mt++) {
                uint32_t off = SWZ64((uint32_t)((wm * 32 + mt * 16 + (lane & 15)) * 64) + chunkb);
                LDSM4(ah[mt], sA + off);
                LDSM4(al[mt], sAl + off);
            }
#pragma unroll
            for (int nt = 0; nt < 4; nt++) {
                uint32_t off = SWZ64((uint32_t)((wn * 64 + nt * 16 + (lane & 15)) * 64) + chunkb);
                uint32_t bh[4], bl[4];
                LDSM4(bh, sB + off);
                LDSM4(bl, sBl + off);
#pragma unroll
                for (int mt = 0; mt < 2; mt++) {
#pragma unroll
                    for (int h2 = 0; h2 < 2; h2++) {
                        const int n8 = nt * 2 + h2;
                        mma16816(cc[mt][n8], ah[mt], bh[h2], bh[h2 + 2]);
                        mma16816(cc[mt][n8], ah[mt], bl[h2], bl[h2 + 2]);
                        mma16816(cc[mt][n8], al[mt], bh[h2], bh[h2 + 2]);
                    }
                }
            }
        }
    }

    // epilogue: add bias, store
#pragma unroll
    for (int mt = 0; mt < 2; mt++) {
        const int rbase = m0 + wm * 32 + mt * 16 + (lane >> 2);
#pragma unroll
        for (int n8 = 0; n8 < 8; n8++) {
            const int col = n0 + wn * 64 + n8 * 8 + (lane & 3) * 2;
            if (col < N_COLS) {
                float2 bv = *(const float2*)(bias + col);
                float2 o0, o1;
                o0.x = cc[mt][n8][0] + bv.x;
                o0.y = cc[mt][n8][1] + bv.y;
                o1.x = cc[mt][n8][2] + bv.x;
                o1.y = cc[mt][n8][3] + bv.y;
                *(float2*)(g_logits + (size_t)rbase * N_COLS + col) = o0;
                *(float2*)(g_logits + (size_t)(rbase + 8) * N_COLS + col) = o1;
            }
        }
    }
}

// ---------------------------------------------------------------------------
// Kernel B: per-row argmax + softmax entropy
// ---------------------------------------------------------------------------
__global__ __launch_bounds__(128)
void rowstats_kernel() {
    const int row = blockIdx.x;
    const float* z = g_logits + (size_t)row * N_COLS;
    const int tid = threadIdx.x;

    __shared__ float smx[128];
    __shared__ int smi[128];
    __shared__ float sS[128];
    __shared__ float sT[128];

    float mx = -3.4e38f;
    int mi = 0x7fffffff;
    for (int c = tid; c < N_COLS; c += 128) {
        float v = z[c];
        if (v > mx) { mx = v; mi = c; }
    }
    smx[tid] = mx; smi[tid] = mi;
    __syncthreads();
    for (int s = 64; s > 0; s >>= 1) {
        if (tid < s) {
            float vo = smx[tid + s]; int io = smi[tid + s];
            if (vo > smx[tid] || (vo == smx[tid] && io < smi[tid])) {
                smx[tid] = vo; smi[tid] = io;
            }
        }
        __syncthreads();
    }
    const float m = smx[0];
    const int vote = smi[0];
    __syncthreads();

    float S = 0.f, T = 0.f;
    for (int c = tid; c < N_COLS; c += 128) {
        float u = z[c] - m;
        float e = expf(u);
        S += e;
        T += u * e;
    }
    sS[tid] = S; sT[tid] = T;
    __syncthreads();
    for (int s = 64; s > 0; s >>= 1) {
        if (tid < s) { sS[tid] += sS[tid + s]; sT[tid] += sT[tid + s]; }
        __syncthreads();
    }
    if (tid == 0) {
        g_ent[row] = logf(sS[0]) - sT[0] / sS[0];
        g_vote[row] = vote;
    }
}

// ---------------------------------------------------------------------------
// Kernel C: per-batch voting
// ---------------------------------------------------------------------------
__global__ __launch_bounds__(256)
void vote_kernel(float* __restrict__ out) {
    __shared__ float ent_s[NUM_TTA_];
    __shared__ int sv[NUM_TTA_];
    __shared__ int counts[N_COLS];
    __shared__ int rmx[256];
    __shared__ int rcnt[256];

    const int b = blockIdx.x;
    const int tid = threadIdx.x;

    if (tid < NUM_TTA_) ent_s[tid] = g_ent[b * NUM_TTA_ + tid];
    for (int c = tid; c < N_COLS; c += 256) counts[c] = 0;
    __syncthreads();

    if (tid < NUM_TTA_) {
        float e = ent_s[tid];
        int r = 0;
#pragma unroll
        for (int j = 0; j < NUM_TTA_; j++) {
            float ej = ent_s[j];
            r += (ej < e) || (ej == e && j < tid);
        }
        sv[r] = g_vote[b * NUM_TTA_ + tid];
    }
    __syncthreads();

    if (tid == 0) {
        for (int i = 0; i < KEPT; i++) counts[sv[i]]++;
    }
    __syncthreads();

    for (int i = 0; i < NUM_TTA_ - KEPT; i++) {
        int mx = -1, cnt = 0;
        for (int c = tid; c < N_COLS; c += 256) {
            int v = counts[c];
            if (v > mx) { mx = v; cnt = 1; }
            else if (v == mx) cnt++;
        }
        rmx[tid] = mx; rcnt[tid] = cnt;
        __syncthreads();
        for (int s = 128; s > 0; s >>= 1) {
            if (tid < s) {
                if (rmx[tid + s] > rmx[tid]) { rmx[tid] = rmx[tid + s]; rcnt[tid] = rcnt[tid + s]; }
                else if (rmx[tid + s] == rmx[tid]) rcnt[tid] += rcnt[tid + s];
            }
            __syncthreads();
        }
        if (tid == 0 && rcnt[0] > 1) counts[sv[KEPT + i]] += 1;
        __syncthreads();
    }

    for (int c = tid; c < N_COLS; c += 256) {
        out[(size_t)b * N_COLS + c] = logf((float)counts[c] * (1.0f / 64.0f) + 1e-8f);
    }
}

// ---------------------------------------------------------------------------
extern "C" void kernel_launch(void* const* d_in, const int* in_sizes, int n_in,
                              void* d_out, int out_size) {
    const float* x = (const float*)d_in[0];
    const float* W = (const float*)d_in[1];
    const float* b = (const float*)d_in[2];
    float* out = (float*)d_out;

    cudaFuncSetAttribute(gemm_fp16x2_kernel,
                         cudaFuncAttributeMaxDynamicSharedMemorySize, SMEM_BYTES);

    split_x_kernel<<<(M_ROWS * (size_t)K_DIM) / 8 / 256, 256>>>(x);
    split_wt_kernel<<<dim3(K_DIM / 32, N_PAD / 32), dim3(32, 32)>>>(W);

    // grid.x = N dim fastest: CTAs sharing an A-tile run concurrently -> A in L2
    gemm_fp16x2_kernel<<<dim3(N_PAD / BN, M_ROWS / BM), 256, SMEM_BYTES>>>(b);

    rowstats_kernel<<<M_ROWS, 128>>>();
    vote_kernel<<<NBATCH, 256>>>(out);
}

// round 7
// speedup vs baseline: 3.5968x; 1.0781x over previous
#include <cuda_runtime.h>
#include <cuda_fp16.h>
#include <cstdint>
#include <math.h>

// ---------------------------------------------------------------------------
// Problem constants
// ---------------------------------------------------------------------------
#define M_ROWS 16384
#define N_COLS 1000
#define N_PAD  1024
#define K_DIM  4096
#define NUM_TTA_ 64
#define KEPT 6
#define NBATCH 256

// GEMM tiling: 128x128 CTA tile, 8 warps (4m x 2n), warp tile 32x64
// BKH=32 halves per k chunk (64 B rows, SW64 swizzle), 3-stage pipeline,
// 96KB smem/CTA -> 2 CTAs per SM.
#define BM 128
#define BN 128
#define BKH 32
#define KITERS (K_DIM / BKH)   // 128
#define NSTAGE 3
#define ARR_BYTES 8192         // 128 rows x 64 B
#define STG_BYTES (4 * ARR_BYTES)   // Ahi|Alo|Bhi|Blo = 32 KB

// ---------------------------------------------------------------------------
// Device-global scratch
// ---------------------------------------------------------------------------
__device__ __half g_xh[(size_t)M_ROWS * K_DIM];
__device__ __half g_xl[(size_t)M_ROWS * K_DIM];
__device__ __half g_wh[(size_t)N_PAD * K_DIM];
__device__ __half g_wl[(size_t)N_PAD * K_DIM];
__device__ float  g_logits[(size_t)M_ROWS * N_COLS];
__device__ float  g_ent[M_ROWS];
__device__ int    g_vote[M_ROWS];

// ---------------------------------------------------------------------------
// PTX helpers
// ---------------------------------------------------------------------------
__device__ __forceinline__ uint32_t smem_u32(const void* p) {
    uint32_t a;
    asm("{ .reg .u64 t; cvta.to.shared.u64 t, %1; cvt.u32.u64 %0, t; }"
        : "=r"(a) : "l"(p));
    return a;
}

// SW64 swizzle: conflict-free ldmatrix on 64B rows
#define SWZ64(o) ((o) ^ (((o) >> 3) & 0x30))

__device__ __forceinline__ void cp16(uint32_t saddr, const void* g) {
    asm volatile("cp.async.cg.shared.global [%0], [%1], 16;"
                 :: "r"(saddr), "l"(g) : "memory");
}

#define LDSM4(R, ADDR) \
    asm volatile("ldmatrix.sync.aligned.m8n8.x4.shared.b16 {%0,%1,%2,%3}, [%4];" \
        : "=r"((R)[0]), "=r"((R)[1]), "=r"((R)[2]), "=r"((R)[3]) : "r"(ADDR))

__device__ __forceinline__ void mma16816(float* c, const uint32_t* a,
                                         uint32_t b0, uint32_t b1) {
    asm volatile(
        "mma.sync.aligned.m16n8k16.row.col.f32.f16.f16.f32 "
        "{%0,%1,%2,%3}, {%4,%5,%6,%7}, {%8,%9}, {%0,%1,%2,%3};"
        : "+f"(c[0]), "+f"(c[1]), "+f"(c[2]), "+f"(c[3])
        : "r"(a[0]), "r"(a[1]), "r"(a[2]), "r"(a[3]), "r"(b0), "r"(b1));
}

// ---------------------------------------------------------------------------
// Pre-pass 1: split x (fp32) -> fp16 hi + fp16 lo residual
// ---------------------------------------------------------------------------
__global__ __launch_bounds__(256)
void split_x_kernel(const float* __restrict__ x) {
    size_t i = ((size_t)blockIdx.x * 256 + threadIdx.x) * 8;
    float4 v0 = *(const float4*)(x + i);
    float4 v1 = *(const float4*)(x + i + 4);
    float f[8] = {v0.x, v0.y, v0.z, v0.w, v1.x, v1.y, v1.z, v1.w};
    __half h[8], l[8];
#pragma unroll
    for (int e = 0; e < 8; e++) {
        h[e] = __float2half_rn(f[e]);
        l[e] = __float2half_rn(f[e] - __half2float(h[e]));
    }
    *(uint4*)(g_xh + i) = *(const uint4*)h;
    *(uint4*)(g_xl + i) = *(const uint4*)l;
}

// ---------------------------------------------------------------------------
// Pre-pass 2: transpose W [K, N] -> [N_PAD, K], split fp16 hi + lo
// ---------------------------------------------------------------------------
__global__ __launch_bounds__(1024)
void split_wt_kernel(const float* __restrict__ W) {
    __shared__ float tile[32][33];
    const int k0 = blockIdx.x * 32;
    const int n0 = blockIdx.y * 32;
    const int tx = threadIdx.x, ty = threadIdx.y;
    const int n = n0 + tx;
    float v = (n < N_COLS) ? W[(size_t)(k0 + ty) * N_COLS + n] : 0.0f;
    tile[ty][tx] = v;
    __syncthreads();
    float u = tile[tx][ty];
    __half h = __float2half_rn(u);
    __half l = __float2half_rn(u - __half2float(h));
    size_t o = (size_t)(n0 + ty) * K_DIM + k0 + tx;
    g_wh[o] = h;
    g_wl[o] = l;
}

// ---------------------------------------------------------------------------
// Kernel A: fp16x2 split GEMM (unchanged R6 core — at legacy-HMMA ceiling)
// ---------------------------------------------------------------------------
#define SMEM_BYTES (NSTAGE * STG_BYTES + 256)

__global__ __launch_bounds__(256, 2)
void gemm_fp16x2_kernel(const float* __restrict__ bias) {
    extern __shared__ char smem_raw[];
    uint32_t sbase = smem_u32(smem_raw);
    sbase = (sbase + 255u) & ~255u;

    const int tid  = threadIdx.x;
    const int lane = tid & 31;
    const int wid  = tid >> 5;
    const int wm   = wid & 3;
    const int wn   = wid >> 2;
    const int m0 = blockIdx.y * BM;
    const int n0 = blockIdx.x * BN;

    const int c0row = tid >> 2;
    const int c0cb  = (tid & 3) * 16;
    const int c1row = (tid + 256) >> 2;
    const uint32_t sw0 = SWZ64((uint32_t)(c0row * 64 + c0cb));
    const uint32_t sw1 = SWZ64((uint32_t)(c1row * 64 + c0cb));

    const __half* gAh0 = g_xh + (size_t)(m0 + c0row) * K_DIM + (c0cb >> 1);
    const __half* gAl0 = g_xl + (size_t)(m0 + c0row) * K_DIM + (c0cb >> 1);
    const __half* gBh0 = g_wh + (size_t)(n0 + c0row) * K_DIM + (c0cb >> 1);
    const __half* gBl0 = g_wl + (size_t)(n0 + c0row) * K_DIM + (c0cb >> 1);
    const __half* gAh1 = g_xh + (size_t)(m0 + c1row) * K_DIM + (c0cb >> 1);
    const __half* gAl1 = g_xl + (size_t)(m0 + c1row) * K_DIM + (c0cb >> 1);
    const __half* gBh1 = g_wh + (size_t)(n0 + c1row) * K_DIM + (c0cb >> 1);
    const __half* gBl1 = g_wl + (size_t)(n0 + c1row) * K_DIM + (c0cb >> 1);

    float cc[2][8][4];
#pragma unroll
    for (int mt = 0; mt < 2; mt++)
#pragma unroll
        for (int n8 = 0; n8 < 8; n8++)
#pragma unroll
            for (int j = 0; j < 4; j++) cc[mt][n8][j] = 0.f;

#define LOAD_STAGE(SB, KH)                                                     \
    do {                                                                       \
        cp16((SB) + 0 * ARR_BYTES + sw0, gAh0 + (KH));                         \
        cp16((SB) + 0 * ARR_BYTES + sw1, gAh1 + (KH));                         \
        cp16((SB) + 1 * ARR_BYTES + sw0, gAl0 + (KH));                         \
        cp16((SB) + 1 * ARR_BYTES + sw1, gAl1 + (KH));                         \
        cp16((SB) + 2 * ARR_BYTES + sw0, gBh0 + (KH));                         \
        cp16((SB) + 2 * ARR_BYTES + sw1, gBh1 + (KH));                         \
        cp16((SB) + 3 * ARR_BYTES + sw0, gBl0 + (KH));                         \
        cp16((SB) + 3 * ARR_BYTES + sw1, gBl1 + (KH));                         \
        asm volatile("cp.async.commit_group;" ::: "memory");                   \
    } while (0)

    LOAD_STAGE(sbase, 0);
    LOAD_STAGE(sbase + STG_BYTES, BKH);

    for (int it = 0; it < KITERS; it++) {
        if (it < KITERS - 1) {
            asm volatile("cp.async.wait_group 1;" ::: "memory");
        } else {
            asm volatile("cp.async.wait_group 0;" ::: "memory");
        }
        __syncthreads();

        if (it + 2 < KITERS) {
            const uint32_t sb = sbase + ((it + 2) % NSTAGE) * STG_BYTES;
            LOAD_STAGE(sb, (it + 2) * BKH);
        }

        const uint32_t sA  = sbase + (it % NSTAGE) * STG_BYTES;
        const uint32_t sAl = sA + 1 * ARR_BYTES;
        const uint32_t sB  = sA + 2 * ARR_BYTES;
        const uint32_t sBl = sA + 3 * ARR_BYTES;

#pragma unroll
        for (int ks = 0; ks < 2; ks++) {
            const uint32_t chunkb = ks * 32 + ((lane >> 4) << 4);
            uint32_t ah[2][4], al[2][4];
#pragma unroll
            for (int mt = 0; mt < 2; mt++) {
                uint32_t off = SWZ64((uint32_t)((wm * 32 + mt * 16 + (lane & 15)) * 64) + chunkb);
                LDSM4(ah[mt], sA + off);
                LDSM4(al[mt], sAl + off);
            }
#pragma unroll
            for (int nt = 0; nt < 4; nt++) {
                uint32_t off = SWZ64((uint32_t)((wn * 64 + nt * 16 + (lane & 15)) * 64) + chunkb);
                uint32_t bh[4], bl[4];
                LDSM4(bh, sB + off);
                LDSM4(bl, sBl + off);
#pragma unroll
                for (int mt = 0; mt < 2; mt++) {
#pragma unroll
                    for (int h2 = 0; h2 < 2; h2++) {
                        const int n8 = nt * 2 + h2;
                        mma16816(cc[mt][n8], ah[mt], bh[h2], bh[h2 + 2]);
                        mma16816(cc[mt][n8], ah[mt], bl[h2], bl[h2 + 2]);
                        mma16816(cc[mt][n8], al[mt], bh[h2], bh[h2 + 2]);
                    }
                }
            }
        }
    }

#pragma unroll
    for (int mt = 0; mt < 2; mt++) {
        const int rbase = m0 + wm * 32 + mt * 16 + (lane >> 2);
#pragma unroll
        for (int n8 = 0; n8 < 8; n8++) {
            const int col = n0 + wn * 64 + n8 * 8 + (lane & 3) * 2;
            if (col < N_COLS) {
                float2 bv = *(const float2*)(bias + col);
                float2 o0, o1;
                o0.x = cc[mt][n8][0] + bv.x;
                o0.y = cc[mt][n8][1] + bv.y;
                o1.x = cc[mt][n8][2] + bv.x;
                o1.y = cc[mt][n8][3] + bv.y;
                *(float2*)(g_logits + (size_t)rbase * N_COLS + col) = o0;
                *(float2*)(g_logits + (size_t)(rbase + 8) * N_COLS + col) = o1;
            }
        }
    }
}

// ---------------------------------------------------------------------------
// Kernel B: warp-per-row argmax + entropy. 8 warps/block, values in regs,
// shfl-only reductions, single gmem pass.
// ---------------------------------------------------------------------------
__global__ __launch_bounds__(256)
void rowstats_kernel() {
    const int lane = threadIdx.x & 31;
    const int row = blockIdx.x * 8 + (threadIdx.x >> 5);
    const float* z = g_logits + (size_t)row * N_COLS;

    // load 8 float4 per lane (indices lane + 32*i, i<8; guard idx<250)
    float4 v[8];
    int nv = 0;
#pragma unroll
    for (int i = 0; i < 8; i++) {
        int idx = lane + 32 * i;
        if (idx < 250) { v[i] = *(const float4*)(z + idx * 4); nv = i + 1; }
    }

    // pass A: max + first-index argmax
    float mx = -3.4e38f;
    int mi = 0x7fffffff;
#pragma unroll
    for (int i = 0; i < 8; i++) {
        int idx = lane + 32 * i;
        if (idx < 250) {
            int c = idx * 4;
            if (v[i].x > mx) { mx = v[i].x; mi = c; }
            if (v[i].y > mx) { mx = v[i].y; mi = c + 1; }
            if (v[i].z > mx) { mx = v[i].z; mi = c + 2; }
            if (v[i].w > mx) { mx = v[i].w; mi = c + 3; }
        }
    }
#pragma unroll
    for (int s = 16; s > 0; s >>= 1) {
        float om = __shfl_xor_sync(0xffffffffu, mx, s);
        int oi = __shfl_xor_sync(0xffffffffu, mi, s);
        if (om > mx || (om == mx && oi < mi)) { mx = om; mi = oi; }
    }

    // pass B: S = sum exp(z-m), T = sum (z-m)exp(z-m)   (from registers)
    float S = 0.f, T = 0.f;
#pragma unroll
    for (int i = 0; i < 8; i++) {
        if (i < nv) {
            float u0 = v[i].x - mx, u1 = v[i].y - mx, u2 = v[i].z - mx, u3 = v[i].w - mx;
            float e0 = expf(u0), e1 = expf(u1), e2 = expf(u2), e3 = expf(u3);
            S += e0 + e1 + e2 + e3;
            T += u0 * e0 + u1 * e1 + u2 * e2 + u3 * e3;
        }
    }
#pragma unroll
    for (int s = 16; s > 0; s >>= 1) {
        S += __shfl_xor_sync(0xffffffffu, S, s);
        T += __shfl_xor_sync(0xffffffffu, T, s);
    }

    if (lane == 0) {
        g_ent[row] = logf(S) - T / S;
        g_vote[row] = mi;
    }
}

// ---------------------------------------------------------------------------
// Kernel C: per-batch voting with O(1) incremental (max, nmax)
// ---------------------------------------------------------------------------
__global__ __launch_bounds__(256)
void vote_kernel(float* __restrict__ out) {
    __shared__ float ent_s[NUM_TTA_];
    __shared__ int sv[NUM_TTA_];
    __shared__ int counts[N_COLS];

    const int b = blockIdx.x;
    const int tid = threadIdx.x;

    if (tid < NUM_TTA_) ent_s[tid] = g_ent[b * NUM_TTA_ + tid];
    for (int c = tid; c < N_COLS; c += 256) counts[c] = 0;
    __syncthreads();

    if (tid < NUM_TTA_) {
        float e = ent_s[tid];
        int r = 0;
#pragma unroll
        for (int j = 0; j < NUM_TTA_; j++) {
            float ej = ent_s[j];
            r += (ej < e) || (ej == e && j < tid);
        }
        sv[r] = g_vote[b * NUM_TTA_ + tid];
    }
    __syncthreads();

    if (tid == 0) {
        // initial counts from top-KEPT votes
        for (int i = 0; i < KEPT; i++) counts[sv[i]]++;
        // initial (max, nmax) over distinct voted classes (all others are 0 < max)
        int mx = 0, nmax = 0;
        for (int i = 0; i < KEPT; i++) {
            int c = sv[i];
            bool first = true;
            for (int j = 0; j < i; j++) if (sv[j] == c) { first = false; break; }
            if (first) {
                int cv = counts[c];
                if (cv > mx) { mx = cv; nmax = 1; }
                else if (cv == mx) nmax++;
            }
        }
        // 58 augmentation steps, O(1) each
        for (int i = 0; i < NUM_TTA_ - KEPT; i++) {
            if (nmax > 1) {
                int c = sv[KEPT + i];
                int nc = counts[c] + 1;
                counts[c] = nc;
                if (nc > mx) { mx = nc; nmax = 1; }
                else if (nc == mx) nmax++;
            }
        }
    }
    __syncthreads();

    for (int c = tid; c < N_COLS; c += 256) {
        out[(size_t)b * N_COLS + c] = logf((float)counts[c] * (1.0f / 64.0f) + 1e-8f);
    }
}

// ---------------------------------------------------------------------------
extern "C" void kernel_launch(void* const* d_in, const int* in_sizes, int n_in,
                              void* d_out, int out_size) {
    const float* x = (const float*)d_in[0];
    const float* W = (const float*)d_in[1];
    const float* b = (const float*)d_in[2];
    float* out = (float*)d_out;

    cudaFuncSetAttribute(gemm_fp16x2_kernel,
                         cudaFuncAttributeMaxDynamicSharedMemorySize, SMEM_BYTES);

    split_x_kernel<<<(M_ROWS * (size_t)K_DIM) / 8 / 256, 256>>>(x);
    split_wt_kernel<<<dim3(K_DIM / 32, N_PAD / 32), dim3(32, 32)>>>(W);

    gemm_fp16x2_kernel<<<dim3(N_PAD / BN, M_ROWS / BM), 256, SMEM_BYTES>>>(b);

    rowstats_kernel<<<M_ROWS / 8, 256>>>();
    vote_kernel<<<NBATCH, 256>>>(out);
}